// round 14
// baseline (speedup 1.0000x reference)
#include <cuda_runtime.h>
#include <cuda_bf16.h>
#include <cstdint>

// Problem constants
#define B_    8
#define N_    8192
#define S_    2048
#define D1_   128
#define D2_   256
#define C0_   384          // D1 + D2
#define O1_   256
#define O2_   128
#define ROWS_ 65536        // B_ * N_
#define BN_EPS_ 1e-5f
#define NPART 8
#define SPART (S_ / NPART)   // 256
#define NCAND (NPART * 3)    // 24

// ---------------- device scratch (no cudaMalloc allowed) ----------------
__device__ __align__(16) __nv_bfloat16 g_Xh[(size_t)ROWS_ * C0_];   // concat hi
__device__ __align__(16) __nv_bfloat16 g_Xl[(size_t)ROWS_ * C0_];   // concat lo
__device__ __align__(16) float g_Y1[(size_t)ROWS_ * O1_];           // layer1 pre-BN
__device__ __align__(16) __nv_bfloat16 g_A2h[(size_t)ROWS_ * O1_];  // BN1+ReLU split hi
__device__ __align__(16) __nv_bfloat16 g_A2l[(size_t)ROWS_ * O1_];  // BN1+ReLU split lo
__device__ __align__(16) float g_Y2[(size_t)ROWS_ * O2_];           // layer2 pre-BN
__device__ __align__(16) float g_f2[(size_t)B_ * S_ * D2_];         // points2 transposed
__device__ __align__(16) float g_cd[(size_t)ROWS_ * NCAND];
__device__ __align__(16) int   g_ci[(size_t)ROWS_ * NCAND];
__device__ float  g_stats1[2 * O1_];
__device__ float  g_stats2[2 * O2_];
__device__ __align__(16) __nv_bfloat16 g_w1h[O1_ * C0_], g_w1l[O1_ * C0_];
__device__ __align__(16) __nv_bfloat16 g_w2h[O2_ * O1_], g_w2l[O2_ * O1_];

// ---------------- helpers ----------------
__device__ __forceinline__ void bsplit2(float a, float b, uint32_t& h, uint32_t& l) {
    __nv_bfloat162 hv, lv;
    hv.x = __float2bfloat16_rn(a);
    hv.y = __float2bfloat16_rn(b);
    lv.x = __float2bfloat16_rn(a - __bfloat162float(hv.x));
    lv.y = __float2bfloat16_rn(b - __bfloat162float(hv.y));
    h = *reinterpret_cast<uint32_t*>(&hv);
    l = *reinterpret_cast<uint32_t*>(&lv);
}

__device__ __forceinline__ void mma16816(float c[4], const uint32_t a[4],
                                         uint32_t b0, uint32_t b1) {
    asm volatile(
        "mma.sync.aligned.m16n8k16.row.col.f32.bf16.bf16.f32 "
        "{%0,%1,%2,%3}, {%4,%5,%6,%7}, {%8,%9}, {%0,%1,%2,%3};"
        : "+f"(c[0]), "+f"(c[1]), "+f"(c[2]), "+f"(c[3])
        : "r"(a[0]), "r"(a[1]), "r"(a[2]), "r"(a[3]), "r"(b0), "r"(b1));
}

__device__ __forceinline__ void ldsm4(uint32_t r[4], uint32_t addr) {
    asm volatile("ldmatrix.sync.aligned.m8n8.x4.shared.b16 {%0,%1,%2,%3}, [%4];"
        : "=r"(r[0]), "=r"(r[1]), "=r"(r[2]), "=r"(r[3]) : "r"(addr));
}

#define CPA16(dst, src) \
    asm volatile("cp.async.cg.shared.global [%0], [%1], 16;" :: "r"(dst), "l"(src))
#define CPA_COMMIT() asm volatile("cp.async.commit_group;" ::: "memory")
#define CPA_WAIT0()  asm volatile("cp.async.wait_group 0;" ::: "memory")
#define CPA_WAIT1()  asm volatile("cp.async.wait_group 1;" ::: "memory")

// SW128-style swizzle on 128B rows: colbyte XOR row(within 8)-keyed 16B lane
__device__ __forceinline__ uint32_t swz128(int row, uint32_t colbyte) {
    return (uint32_t)(row * 128) + (colbyte ^ (uint32_t)((row & 7) << 4));
}

// ---------------- fused prep + 3-NN (co-scheduled) ----------------
#define NN_BLKS  2048
#define PRE_BLKS 384
#define TRF2_BLKS 4096
#define TRF1_BLKS 8192
__global__ __launch_bounds__(256) void k_prep(const float* __restrict__ xyz1,
                      const float* __restrict__ xyz2,
                      const float* __restrict__ w1, const float* __restrict__ w2,
                      const float* __restrict__ points2, const float* __restrict__ points1) {
    __shared__ float tile[32][33];
    __shared__ float4 sp[SPART];
    int bid = blockIdx.x;
    int tid = threadIdx.x;
    if (bid < NN_BLKS) {
        int b    = bid >> 8;
        int rem  = bid & 255;
        int part = rem >> 5;
        int n    = (rem & 31) * 256 + tid;
        {
            const float* p = xyz2 + (size_t)b * 3 * S_ + part * SPART;
            float x = p[tid], y = p[S_ + tid], z = p[2 * S_ + tid];
            sp[tid] = make_float4(x, y, z, x * x + y * y + z * z);
        }
        __syncthreads();

        const float* q = xyz1 + (size_t)b * 3 * N_;
        float x = q[n], y = q[N_ + n], z = q[2 * N_ + n];
        float nx = -2.f * x, ny = -2.f * y, nz = -2.f * z;

        float d0 = 1e30f, d1 = 1e30f, d2 = 1e30f;
        int i0 = 0, i1 = 0, i2 = 0;
        #pragma unroll 8
        for (int s = 0; s < SPART; s++) {
            float4 p = sp[s];
            float d = fmaf(p.x, nx, fmaf(p.y, ny, fmaf(p.z, nz, p.w)));
            if (d < d2) {
                if (d < d1) {
                    d2 = d1; i2 = i1;
                    if (d < d0) { d1 = d0; i1 = i0; d0 = d; i0 = s; }
                    else        { d1 = d;  i1 = s; }
                } else { d2 = d; i2 = s; }
            }
        }
        size_t row = (size_t)b * N_ + n;
        size_t o = row * NCAND + part * 3;
        int base = part * SPART;
        g_cd[o + 0] = d0; g_cd[o + 1] = d1; g_cd[o + 2] = d2;
        g_ci[o + 0] = base + i0; g_ci[o + 1] = base + i1; g_ci[o + 2] = base + i2;
    } else if (bid < NN_BLKS + PRE_BLKS) {
        int t = (bid - NN_BLKS) * 256 + tid;
        if (t < 2 * O1_) g_stats1[t] = 0.f;
        if (t < 2 * O2_) g_stats2[t] = 0.f;
        if (t < O1_ * C0_) {
            float v = w1[t];
            __nv_bfloat16 h = __float2bfloat16_rn(v);
            g_w1h[t] = h;
            g_w1l[t] = __float2bfloat16_rn(v - __bfloat162float(h));
        }
        if (t < O2_ * O1_) {
            float v = w2[t];
            __nv_bfloat16 h = __float2bfloat16_rn(v);
            g_w2h[t] = h;
            g_w2l[t] = __float2bfloat16_rn(v - __bfloat162float(h));
        }
    } else if (bid < NN_BLKS + PRE_BLKS + TRF2_BLKS) {
        int rel = bid - NN_BLKS - PRE_BLKS;
        int s0 = (rel & 63) * 32;
        int d0 = ((rel >> 6) & 7) * 32;
        int b  = rel >> 9;
        int tx = tid & 31, ty = tid >> 5;
        const float* src = points2 + ((size_t)b * D2_ + d0) * S_ + s0;
        #pragma unroll
        for (int i = ty; i < 32; i += 8)
            tile[i][tx] = src[(size_t)i * S_ + tx];
        __syncthreads();
        float* dst = g_f2 + ((size_t)b * S_ + s0) * D2_ + d0;
        #pragma unroll
        for (int i = ty; i < 32; i += 8)
            dst[(size_t)i * D2_ + tx] = tile[tx][i];
    } else {
        int rel = bid - NN_BLKS - PRE_BLKS - TRF2_BLKS;
        int n0 = (rel & 255) * 32;
        int d0 = ((rel >> 8) & 3) * 32;
        int b  = rel >> 10;
        int tx = tid & 31, ty = tid >> 5;
        const float* src = points1 + ((size_t)b * D1_ + d0) * N_ + n0;
        #pragma unroll
        for (int i = ty; i < 32; i += 8)
            tile[i][tx] = src[(size_t)i * N_ + tx];
        __syncthreads();
        size_t base = ((size_t)(b * N_ + n0)) * C0_ + d0;
        #pragma unroll
        for (int i = ty; i < 32; i += 8) {
            float v = tile[tx][i];
            __nv_bfloat16 h = __float2bfloat16_rn(v);
            g_Xh[base + (size_t)i * C0_ + tx] = h;
            g_Xl[base + (size_t)i * C0_ + tx] = __float2bfloat16_rn(v - __bfloat162float(h));
        }
    }
}

// ---------------- fused merge(24->3) + gather + interpolate -> split bf16 ----------------
__global__ __launch_bounds__(256) void k_interp(const float* __restrict__ xyz1) {
    __shared__ int   sidx[4][3];
    __shared__ float swt [4][3];
    int t = threadIdx.x;
    if (t < 4) {
        unsigned row = blockIdx.x * 4 + t;
        int b = row / N_, n = row % N_;
        float d0 = 1e30f, d1 = 1e30f, d2 = 1e30f;
        int i0 = 0, i1 = 0, i2 = 0;
        const float* cd = g_cd + (size_t)row * NCAND;
        const int*   ci = g_ci + (size_t)row * NCAND;
        #pragma unroll
        for (int j = 0; j < NCAND; j++) {
            float d = cd[j]; int ix = ci[j];
            if (d < d2) {
                if (d < d1) {
                    d2 = d1; i2 = i1;
                    if (d < d0) { d1 = d0; i1 = i0; d0 = d; i0 = ix; }
                    else        { d1 = d;  i1 = ix; }
                } else { d2 = d; i2 = ix; }
            }
        }
        const float* q = xyz1 + (size_t)b * 3 * N_;
        float x = q[n], y = q[N_ + n], z = q[2 * N_ + n];
        float r1 = x * x + y * y + z * z;
        float t0 = fmaxf(d0 + r1, 1e-10f);
        float t1 = fmaxf(d1 + r1, 1e-10f);
        float t2 = fmaxf(d2 + r1, 1e-10f);
        float w0 = 1.f / t0, w1 = 1.f / t1, w2 = 1.f / t2;
        float inv = 1.f / (w0 + w1 + w2);
        sidx[t][0] = i0; sidx[t][1] = i1; sidx[t][2] = i2;
        swt [t][0] = w0 * inv; swt[t][1] = w1 * inv; swt[t][2] = w2 * inv;
    }
    __syncthreads();
    int lr = t >> 6, ln = t & 63;
    unsigned row = blockIdx.x * 4 + lr;
    int b = row / N_;
    int  i0 = sidx[lr][0], i1 = sidx[lr][1], i2 = sidx[lr][2];
    float w0 = swt[lr][0], w1 = swt[lr][1], w2 = swt[lr][2];
    const float4* f = (const float4*)(g_f2 + (size_t)b * S_ * D2_);
    float4 v0 = f[(size_t)i0 * 64 + ln];
    float4 v1 = f[(size_t)i1 * 64 + ln];
    float4 v2 = f[(size_t)i2 * 64 + ln];
    float4 v;
    v.x = w0 * v0.x + w1 * v1.x + w2 * v2.x;
    v.y = w0 * v0.y + w1 * v1.y + w2 * v2.y;
    v.z = w0 * v0.z + w1 * v1.z + w2 * v2.z;
    v.w = w0 * v0.w + w1 * v1.w + w2 * v2.w;
    uint2 hq, lq;
    bsplit2(v.x, v.y, hq.x, lq.x);
    bsplit2(v.z, v.w, hq.y, lq.y);
    size_t o = (size_t)row * C0_ + D1_ + ln * 4;
    *(uint2*)&g_Xh[o] = hq;
    *(uint2*)&g_Xl[o] = lq;
}

// ---------------- HMMA bf16-split GEMM: 128x128 tile, 512 threads, K-chunk 64, 3-stage ----------------
// 16 warps in 4x4 grid, warp tile 32x32. Stage: 4 regions x 16KB (128 rows x 128B SW128).
#define OFF_AH 0
#define OFF_AL 16384
#define OFF_BH 32768
#define OFF_BL 49152
#define STG_BYTES 65536

template<int LAYER>
__global__ __launch_bounds__(512, 1) void k_gemm_cpa(const float* __restrict__ bias) {
    constexpr bool L1 = (LAYER == 1);
    constexpr int KD = L1 ? C0_ : O1_;
    constexpr int NO = L1 ? O1_ : O2_;
    constexpr int NCH = KD / 64;           // 6 for L1, 4 for L2

    const __nv_bfloat16* __restrict__ Ah = L1 ? g_Xh : g_A2h;
    const __nv_bfloat16* __restrict__ Al = L1 ? g_Xl : g_A2l;
    const __nv_bfloat16* __restrict__ Wh = L1 ? g_w1h : g_w2h;
    const __nv_bfloat16* __restrict__ Wl = L1 ? g_w1l : g_w2l;
    float* __restrict__ Y     = L1 ? g_Y1 : g_Y2;
    float* __restrict__ stats = L1 ? g_stats1 : g_stats2;

    extern __shared__ char sm[];
    const uint32_t smbase = (uint32_t)__cvta_generic_to_shared(sm);

    const int tid = threadIdx.x;
    const int lane = tid & 31, wid = tid >> 5;
    const int g = lane >> 2, tig = lane & 3;
    const int wm = wid & 3, wn = wid >> 2;      // 4 x 4 warp grid; warp tile 32x32
    const int r0 = blockIdx.x * 128;
    const int n0 = blockIdx.y * 128;

    float acc[2][4][4];
    #pragma unroll
    for (int m = 0; m < 2; m++)
        #pragma unroll
        for (int n = 0; n < 4; n++)
            #pragma unroll
            for (int j = 0; j < 4; j++) acc[m][n][j] = 0.f;

    // ldmatrix per-thread row/col (swizzled at use-time)
    const int a_row = wm * 32 + (lane & 15);
    const uint32_t a_colb = (uint32_t)((lane >> 4) * 16);
    const int b_row_base = wn * 32 + ((lane >> 4) << 3) + (lane & 7);
    const uint32_t b_colb = (uint32_t)(((lane >> 3) & 1) * 16);

    // cp.async: row = tid>>2 (0..127), two 16B segs at (tid&3)*32
    const int crow = tid >> 2;
    const uint32_t csegb = (uint32_t)((tid & 3) * 32);

#define CPA_CHUNK(buf, kc) do {                                                   \
        uint32_t bb = smbase + (uint32_t)((buf) * STG_BYTES);                     \
        uint32_t d0o = swz128(crow, csegb);                                       \
        uint32_t d1o = swz128(crow, csegb + 16);                                  \
        const char* sA_h = (const char*)&Ah[(size_t)(r0 + crow) * KD + (kc)];     \
        const char* sA_l = (const char*)&Al[(size_t)(r0 + crow) * KD + (kc)];     \
        const char* sB_h = (const char*)&Wh[(size_t)(n0 + crow) * KD + (kc)];     \
        const char* sB_l = (const char*)&Wl[(size_t)(n0 + crow) * KD + (kc)];     \
        CPA16(bb + OFF_AH + d0o, sA_h + csegb);                                   \
        CPA16(bb + OFF_AH + d1o, sA_h + csegb + 16);                              \
        CPA16(bb + OFF_AL + d0o, sA_l + csegb);                                   \
        CPA16(bb + OFF_AL + d1o, sA_l + csegb + 16);                              \
        CPA16(bb + OFF_BH + d0o, sB_h + csegb);                                   \
        CPA16(bb + OFF_BH + d1o, sB_h + csegb + 16);                              \
        CPA16(bb + OFF_BL + d0o, sB_l + csegb);                                   \
        CPA16(bb + OFF_BL + d1o, sB_l + csegb + 16);                              \
        CPA_COMMIT();                                                             \
    } while (0)

#define COMPUTE_CHUNK(buf) do {                                                   \
        const uint32_t bufb = smbase + (uint32_t)((buf) * STG_BYTES);             \
        _Pragma("unroll")                                                         \
        for (int ko = 0; ko < 4; ko++) {                                          \
            const uint32_t kb = (uint32_t)(ko * 32);                              \
            uint32_t bh01[4], bl01[4], bh23[4], bl23[4];                          \
            ldsm4(bh01, bufb + OFF_BH + swz128(b_row_base,      b_colb + kb));    \
            ldsm4(bl01, bufb + OFF_BL + swz128(b_row_base,      b_colb + kb));    \
            ldsm4(bh23, bufb + OFF_BH + swz128(b_row_base + 16, b_colb + kb));    \
            ldsm4(bl23, bufb + OFF_BL + swz128(b_row_base + 16, b_colb + kb));    \
            _Pragma("unroll")                                                     \
            for (int mt = 0; mt < 2; mt++) {                                      \
                uint32_t ah[4], al[4];                                            \
                uint32_t ao = swz128(a_row + mt * 16, a_colb + kb);               \
                ldsm4(ah, bufb + OFF_AH + ao);                                    \
                ldsm4(al, bufb + OFF_AL + ao);                                    \
                mma16816(acc[mt][0], ah, bh01[0], bh01[1]);                       \
                mma16816(acc[mt][1], ah, bh01[2], bh01[3]);                       \
                mma16816(acc[mt][2], ah, bh23[0], bh23[1]);                       \
                mma16816(acc[mt][3], ah, bh23[2], bh23[3]);                       \
                mma16816(acc[mt][0], ah, bl01[0], bl01[1]);                       \
                mma16816(acc[mt][1], ah, bl01[2], bl01[3]);                       \
                mma16816(acc[mt][2], ah, bl23[0], bl23[1]);                       \
                mma16816(acc[mt][3], ah, bl23[2], bl23[3]);                       \
                mma16816(acc[mt][0], al, bh01[0], bh01[1]);                       \
                mma16816(acc[mt][1], al, bh01[2], bh01[3]);                       \
                mma16816(acc[mt][2], al, bh23[0], bh23[1]);                       \
                mma16816(acc[mt][3], al, bh23[2], bh23[3]);                       \
            }                                                                     \
        }                                                                         \
    } while (0)

    // 3-stage pipeline, single barrier per chunk
    CPA_CHUNK(0, 0);
    CPA_CHUNK(1, 64);
    int st = 0;
    for (int ch = 0; ch < NCH; ch++) {
        if (ch + 1 < NCH) CPA_WAIT1(); else CPA_WAIT0();
        __syncthreads();
        if (ch + 2 < NCH) {
            int st2 = st + 2; if (st2 >= 3) st2 -= 3;
            CPA_CHUNK(st2, (ch + 2) * 64);
        }
        COMPUTE_CHUNK(st);
        if (++st == 3) st = 0;
    }
#undef CPA_CHUNK
#undef COMPUTE_CHUNK

    // ---- epilogue: + bias, store float, fused per-channel BN stats
    float ssum[4][2], ssq[4][2];
    #pragma unroll
    for (int nt = 0; nt < 4; nt++) { ssum[nt][0] = ssum[nt][1] = 0.f; ssq[nt][0] = ssq[nt][1] = 0.f; }

    #pragma unroll
    for (int mt = 0; mt < 2; mt++) {
        int row = r0 + wm * 32 + mt * 16 + g;
        #pragma unroll
        for (int nt = 0; nt < 4; nt++) {
            int col = n0 + wn * 32 + nt * 8 + 2 * tig;
            float bv0 = __ldg(bias + col), bv1 = __ldg(bias + col + 1);
            float v0 = acc[mt][nt][0] + bv0, v1 = acc[mt][nt][1] + bv1;
            float v2 = acc[mt][nt][2] + bv0, v3 = acc[mt][nt][3] + bv1;
            ssum[nt][0] += v0 + v2;  ssum[nt][1] += v1 + v3;
            ssq[nt][0]  += v0 * v0 + v2 * v2;
            ssq[nt][1]  += v1 * v1 + v3 * v3;
            *(float2*)&Y[(size_t)row * NO + col]       = make_float2(v0, v1);
            *(float2*)&Y[(size_t)(row + 8) * NO + col] = make_float2(v2, v3);
        }
    }

    #pragma unroll
    for (int nt = 0; nt < 4; nt++)
        #pragma unroll
        for (int c = 0; c < 2; c++) {
            float s = ssum[nt][c], q = ssq[nt][c];
            s += __shfl_xor_sync(0xFFFFFFFFu, s, 4);
            s += __shfl_xor_sync(0xFFFFFFFFu, s, 8);
            s += __shfl_xor_sync(0xFFFFFFFFu, s, 16);
            q += __shfl_xor_sync(0xFFFFFFFFu, q, 4);
            q += __shfl_xor_sync(0xFFFFFFFFu, q, 8);
            q += __shfl_xor_sync(0xFFFFFFFFu, q, 16);
            if (g == 0) {
                int col = n0 + wn * 32 + nt * 8 + 2 * tig + c;
                atomicAdd(&stats[col], s);
                atomicAdd(&stats[NO + col], q);
            }
        }
}

// ---------------- BN1 finalize (inline) + ReLU + split: Y1(float) -> A2(bf16 h/l) ----------------
__global__ __launch_bounds__(256) void k_bnsplit(const float* __restrict__ g1,
                                                 const float* __restrict__ be1) {
    __shared__ float ssc[O1_], ssh[O1_];
    int tid = threadIdx.x;
    {
        int c = tid;
        float mean = g_stats1[c] * (1.0f / ROWS_);
        float var  = g_stats1[O1_ + c] * (1.0f / ROWS_) - mean * mean;
        float rstd = rsqrtf(var + BN_EPS_);
        float sc = g1[c] * rstd;
        ssc[c] = sc;
        ssh[c] = be1[c] - mean * sc;
    }
    __syncthreads();
    int lr = tid >> 6, ln = tid & 63;
    size_t row = (size_t)blockIdx.x * 4 + lr;
    size_t base = row * O1_ + ln * 4;
    float4 y = *(const float4*)&g_Y1[base];
    int c0 = ln * 4;
    float v0 = fmaxf(fmaf(y.x, ssc[c0 + 0], ssh[c0 + 0]), 0.f);
    float v1 = fmaxf(fmaf(y.y, ssc[c0 + 1], ssh[c0 + 1]), 0.f);
    float v2 = fmaxf(fmaf(y.z, ssc[c0 + 2], ssh[c0 + 2]), 0.f);
    float v3 = fmaxf(fmaf(y.w, ssc[c0 + 3], ssh[c0 + 3]), 0.f);
    uint2 oh, ol;
    bsplit2(v0, v1, oh.x, ol.x);
    bsplit2(v2, v3, oh.y, ol.y);
    *(uint2*)&g_A2h[base] = oh;
    *(uint2*)&g_A2l[base] = ol;
}

// ---------------- BN2(inline finalize) + ReLU + transpose to output ----------------
__global__ void k_out(float* __restrict__ out,
                      const float* __restrict__ g2, const float* __restrict__ be2) {
    __shared__ float tile[32][33];
    int b = blockIdx.z;
    int n0 = blockIdx.x * 32, o0 = blockIdx.y * 32;
    int tx = threadIdx.x, ty = threadIdx.y;
    int c = o0 + tx;
    float mean = g_stats2[c] * (1.0f / ROWS_);
    float var  = g_stats2[O2_ + c] * (1.0f / ROWS_) - mean * mean;
    float rstd = rsqrtf(var + BN_EPS_);
    float sc = g2[c] * rstd;
    float sh = be2[c] - mean * sc;
    const float* src = g_Y2 + ((size_t)(b * N_ + n0)) * O2_ + o0;
    #pragma unroll
    for (int i = ty; i < 32; i += 8) {
        float v = src[(size_t)i * O2_ + tx];
        tile[i][tx] = fmaxf(fmaf(v, sc, sh), 0.f);
    }
    __syncthreads();
    float* dst = out + ((size_t)b * O2_ + o0) * N_ + n0;
    #pragma unroll
    for (int i = ty; i < 32; i += 8)
        dst[(size_t)i * N_ + tx] = tile[tx][i];
}

// ---------------- launch ----------------
extern "C" void kernel_launch(void* const* d_in, const int* in_sizes, int n_in,
                              void* d_out, int out_size) {
    (void)in_sizes; (void)n_in; (void)out_size;
    const float* xyz1    = (const float*)d_in[0];
    const float* xyz2    = (const float*)d_in[1];
    const float* points1 = (const float*)d_in[2];
    const float* points2 = (const float*)d_in[3];
    const float* w1  = (const float*)d_in[4];
    const float* b1  = (const float*)d_in[5];
    const float* g1  = (const float*)d_in[6];
    const float* be1 = (const float*)d_in[7];
    const float* w2  = (const float*)d_in[8];
    const float* b2  = (const float*)d_in[9];
    const float* g2  = (const float*)d_in[10];
    const float* be2 = (const float*)d_in[11];
    float* out = (float*)d_out;

    const int SMEM = 3 * STG_BYTES;   // 196608 per CTA (1 CTA/SM)
    cudaFuncSetAttribute(k_gemm_cpa<1>, cudaFuncAttributeMaxDynamicSharedMemorySize, SMEM);
    cudaFuncSetAttribute(k_gemm_cpa<2>, cudaFuncAttributeMaxDynamicSharedMemorySize, SMEM);

    k_prep<<<NN_BLKS + PRE_BLKS + TRF2_BLKS + TRF1_BLKS, 256>>>(
        xyz1, xyz2, w1, w2, points2, points1);                                     // 0
    k_interp<<<ROWS_ / 4, 256>>>(xyz1);                                            // 1
    k_gemm_cpa<1><<<dim3(ROWS_ / 128, 2), 512, SMEM>>>(b1);                        // 2
    k_bnsplit<<<ROWS_ / 4, 256>>>(g1, be1);                                        // 3
    k_gemm_cpa<2><<<dim3(ROWS_ / 128, 1), 512, SMEM>>>(b2);                        // 4
    k_out<<<dim3(N_ / 32, O2_ / 32, B_), dim3(32, 8)>>>(out, g2, be2);             // 5
}

// round 15
// speedup vs baseline: 1.1375x; 1.1375x over previous
#include <cuda_runtime.h>
#include <cuda_bf16.h>
#include <cstdint>

// Problem constants
#define B_    8
#define N_    8192
#define S_    2048
#define D1_   128
#define D2_   256
#define C0_   384          // D1 + D2
#define O1_   256
#define O2_   128
#define ROWS_ 65536        // B_ * N_
#define BN_EPS_ 1e-5f
#define NPART 8
#define SPART (S_ / NPART)   // 256
#define NCAND (NPART * 3)    // 24

// ---------------- device scratch (no cudaMalloc allowed) ----------------
__device__ __align__(16) __nv_bfloat16 g_Xh[(size_t)ROWS_ * C0_];   // concat hi
__device__ __align__(16) __nv_bfloat16 g_Xl[(size_t)ROWS_ * C0_];   // concat lo
__device__ __align__(16) float g_Y1[(size_t)ROWS_ * O1_];           // layer1 pre-BN
__device__ __align__(16) __nv_bfloat16 g_A2h[(size_t)ROWS_ * O1_];  // BN1+ReLU split hi
__device__ __align__(16) __nv_bfloat16 g_A2l[(size_t)ROWS_ * O1_];  // BN1+ReLU split lo
__device__ __align__(16) float g_Y2[(size_t)ROWS_ * O2_];           // layer2 pre-BN
__device__ __align__(16) float g_f2[(size_t)B_ * S_ * D2_];         // points2 transposed
__device__ __align__(16) float g_cd[(size_t)ROWS_ * NCAND];
__device__ __align__(16) int   g_ci[(size_t)ROWS_ * NCAND];
__device__ float  g_stats1[2 * O1_];
__device__ float  g_stats2[2 * O2_];
__device__ __align__(16) __nv_bfloat16 g_w1h[O1_ * C0_], g_w1l[O1_ * C0_];
__device__ __align__(16) __nv_bfloat16 g_w2h[O2_ * O1_], g_w2l[O2_ * O1_];

// ---------------- helpers ----------------
__device__ __forceinline__ void bsplit2(float a, float b, uint32_t& h, uint32_t& l) {
    __nv_bfloat162 hv, lv;
    hv.x = __float2bfloat16_rn(a);
    hv.y = __float2bfloat16_rn(b);
    lv.x = __float2bfloat16_rn(a - __bfloat162float(hv.x));
    lv.y = __float2bfloat16_rn(b - __bfloat162float(hv.y));
    h = *reinterpret_cast<uint32_t*>(&hv);
    l = *reinterpret_cast<uint32_t*>(&lv);
}

__device__ __forceinline__ void mma16816(float c[4], const uint32_t a[4],
                                         uint32_t b0, uint32_t b1) {
    asm volatile(
        "mma.sync.aligned.m16n8k16.row.col.f32.bf16.bf16.f32 "
        "{%0,%1,%2,%3}, {%4,%5,%6,%7}, {%8,%9}, {%0,%1,%2,%3};"
        : "+f"(c[0]), "+f"(c[1]), "+f"(c[2]), "+f"(c[3])
        : "r"(a[0]), "r"(a[1]), "r"(a[2]), "r"(a[3]), "r"(b0), "r"(b1));
}

__device__ __forceinline__ void ldsm4(uint32_t r[4], uint32_t addr) {
    asm volatile("ldmatrix.sync.aligned.m8n8.x4.shared.b16 {%0,%1,%2,%3}, [%4];"
        : "=r"(r[0]), "=r"(r[1]), "=r"(r[2]), "=r"(r[3]) : "r"(addr));
}

#define CPA16(dst, src) \
    asm volatile("cp.async.cg.shared.global [%0], [%1], 16;" :: "r"(dst), "l"(src))
#define CPA_COMMIT() asm volatile("cp.async.commit_group;" ::: "memory")
#define CPA_WAIT0()  asm volatile("cp.async.wait_group 0;" ::: "memory")
#define CPA_WAIT1()  asm volatile("cp.async.wait_group 1;" ::: "memory")

// row-swizzled 64B-row smem layout: addr = row*64 + (colbyte ^ ((row*8)&0x30))
__device__ __forceinline__ uint32_t swz64(int row, uint32_t colbyte) {
    return (uint32_t)(row * 64) + (colbyte ^ (uint32_t)((row * 8) & 0x30));
}

// ---------------- fused prep + 3-NN, role-INTERLEAVED for DRAM/ALU overlap ----------------
// every 7th block (bid%7==0, bid/7<2048) is an nn3p block; others map in order to
// misc/weights, tr_f2, tr_f1.
#define NN_BLKS  2048
#define PRE_BLKS 384
#define TRF2_BLKS 4096
#define TRF1_BLKS 8192
#define TOT_BLKS (NN_BLKS + PRE_BLKS + TRF2_BLKS + TRF1_BLKS)   // 14720
__global__ __launch_bounds__(256) void k_prep(const float* __restrict__ xyz1,
                      const float* __restrict__ xyz2,
                      const float* __restrict__ w1, const float* __restrict__ w2,
                      const float* __restrict__ points2, const float* __restrict__ points1) {
    __shared__ float tile[32][33];
    __shared__ float4 sp[SPART];
    int bid0 = blockIdx.x;
    int tid = threadIdx.x;
    bool is_nn = ((bid0 % 7) == 0) && (bid0 / 7 < NN_BLKS);
    int nn_before = (bid0 == 0) ? 0 : min(NN_BLKS, (bid0 - 1) / 7 + 1);

    if (is_nn) {
        int bid = bid0 / 7;
        int b    = bid >> 8;
        int rem  = bid & 255;
        int part = rem >> 5;
        int n    = (rem & 31) * 256 + tid;
        {
            const float* p = xyz2 + (size_t)b * 3 * S_ + part * SPART;
            float x = p[tid], y = p[S_ + tid], z = p[2 * S_ + tid];
            sp[tid] = make_float4(x, y, z, x * x + y * y + z * z);
        }
        __syncthreads();

        const float* q = xyz1 + (size_t)b * 3 * N_;
        float x = q[n], y = q[N_ + n], z = q[2 * N_ + n];
        float nx = -2.f * x, ny = -2.f * y, nz = -2.f * z;

        float d0 = 1e30f, d1 = 1e30f, d2 = 1e30f;
        int i0 = 0, i1 = 0, i2 = 0;
        #pragma unroll 8
        for (int s = 0; s < SPART; s++) {
            float4 p = sp[s];
            float d = fmaf(p.x, nx, fmaf(p.y, ny, fmaf(p.z, nz, p.w)));
            if (d < d2) {
                if (d < d1) {
                    d2 = d1; i2 = i1;
                    if (d < d0) { d1 = d0; i1 = i0; d0 = d; i0 = s; }
                    else        { d1 = d;  i1 = s; }
                } else { d2 = d; i2 = s; }
            }
        }
        size_t row = (size_t)b * N_ + n;
        size_t o = row * NCAND + part * 3;
        int base = part * SPART;
        g_cd[o + 0] = d0; g_cd[o + 1] = d1; g_cd[o + 2] = d2;
        g_ci[o + 0] = base + i0; g_ci[o + 1] = base + i1; g_ci[o + 2] = base + i2;
        return;
    }

    int bid = bid0 - nn_before;      // 0..12671
    if (bid < PRE_BLKS) {
        int t = bid * 256 + tid;
        if (t < 2 * O1_) g_stats1[t] = 0.f;
        if (t < 2 * O2_) g_stats2[t] = 0.f;
        if (t < O1_ * C0_) {
            float v = w1[t];
            __nv_bfloat16 h = __float2bfloat16_rn(v);
            g_w1h[t] = h;
            g_w1l[t] = __float2bfloat16_rn(v - __bfloat162float(h));
        }
        if (t < O2_ * O1_) {
            float v = w2[t];
            __nv_bfloat16 h = __float2bfloat16_rn(v);
            g_w2h[t] = h;
            g_w2l[t] = __float2bfloat16_rn(v - __bfloat162float(h));
        }
    } else if (bid < PRE_BLKS + TRF2_BLKS) {
        int rel = bid - PRE_BLKS;
        int s0 = (rel & 63) * 32;
        int d0 = ((rel >> 6) & 7) * 32;
        int b  = rel >> 9;
        int tx = tid & 31, ty = tid >> 5;
        const float* src = points2 + ((size_t)b * D2_ + d0) * S_ + s0;
        #pragma unroll
        for (int i = ty; i < 32; i += 8)
            tile[i][tx] = src[(size_t)i * S_ + tx];
        __syncthreads();
        float* dst = g_f2 + ((size_t)b * S_ + s0) * D2_ + d0;
        #pragma unroll
        for (int i = ty; i < 32; i += 8)
            dst[(size_t)i * D2_ + tx] = tile[tx][i];
    } else {
        int rel = bid - PRE_BLKS - TRF2_BLKS;
        int n0 = (rel & 255) * 32;
        int d0 = ((rel >> 8) & 3) * 32;
        int b  = rel >> 10;
        int tx = tid & 31, ty = tid >> 5;
        const float* src = points1 + ((size_t)b * D1_ + d0) * N_ + n0;
        #pragma unroll
        for (int i = ty; i < 32; i += 8)
            tile[i][tx] = src[(size_t)i * N_ + tx];
        __syncthreads();
        size_t base = ((size_t)(b * N_ + n0)) * C0_ + d0;
        #pragma unroll
        for (int i = ty; i < 32; i += 8) {
            float v = tile[tx][i];
            __nv_bfloat16 h = __float2bfloat16_rn(v);
            g_Xh[base + (size_t)i * C0_ + tx] = h;
            g_Xl[base + (size_t)i * C0_ + tx] = __float2bfloat16_rn(v - __bfloat162float(h));
        }
    }
}

// ---------------- fused merge(24->3) + gather + interpolate -> split bf16 ----------------
__global__ __launch_bounds__(256) void k_interp(const float* __restrict__ xyz1) {
    __shared__ int   sidx[4][3];
    __shared__ float swt [4][3];
    int t = threadIdx.x;
    if (t < 4) {
        unsigned row = blockIdx.x * 4 + t;
        int b = row / N_, n = row % N_;
        float d0 = 1e30f, d1 = 1e30f, d2 = 1e30f;
        int i0 = 0, i1 = 0, i2 = 0;
        const float* cd = g_cd + (size_t)row * NCAND;
        const int*   ci = g_ci + (size_t)row * NCAND;
        #pragma unroll
        for (int j = 0; j < NCAND; j++) {
            float d = cd[j]; int ix = ci[j];
            if (d < d2) {
                if (d < d1) {
                    d2 = d1; i2 = i1;
                    if (d < d0) { d1 = d0; i1 = i0; d0 = d; i0 = ix; }
                    else        { d1 = d;  i1 = ix; }
                } else { d2 = d; i2 = ix; }
            }
        }
        const float* q = xyz1 + (size_t)b * 3 * N_;
        float x = q[n], y = q[N_ + n], z = q[2 * N_ + n];
        float r1 = x * x + y * y + z * z;
        float t0 = fmaxf(d0 + r1, 1e-10f);
        float t1 = fmaxf(d1 + r1, 1e-10f);
        float t2 = fmaxf(d2 + r1, 1e-10f);
        float w0 = 1.f / t0, w1 = 1.f / t1, w2 = 1.f / t2;
        float inv = 1.f / (w0 + w1 + w2);
        sidx[t][0] = i0; sidx[t][1] = i1; sidx[t][2] = i2;
        swt [t][0] = w0 * inv; swt[t][1] = w1 * inv; swt[t][2] = w2 * inv;
    }
    __syncthreads();
    int lr = t >> 6, ln = t & 63;
    unsigned row = blockIdx.x * 4 + lr;
    int b = row / N_;
    int  i0 = sidx[lr][0], i1 = sidx[lr][1], i2 = sidx[lr][2];
    float w0 = swt[lr][0], w1 = swt[lr][1], w2 = swt[lr][2];
    const float4* f = (const float4*)(g_f2 + (size_t)b * S_ * D2_);
    float4 v0 = f[(size_t)i0 * 64 + ln];
    float4 v1 = f[(size_t)i1 * 64 + ln];
    float4 v2 = f[(size_t)i2 * 64 + ln];
    float4 v;
    v.x = w0 * v0.x + w1 * v1.x + w2 * v2.x;
    v.y = w0 * v0.y + w1 * v1.y + w2 * v2.y;
    v.z = w0 * v0.z + w1 * v1.z + w2 * v2.z;
    v.w = w0 * v0.w + w1 * v1.w + w2 * v2.w;
    uint2 hq, lq;
    bsplit2(v.x, v.y, hq.x, lq.x);
    bsplit2(v.z, v.w, hq.y, lq.y);
    size_t o = (size_t)row * C0_ + D1_ + ln * 4;
    *(uint2*)&g_Xh[o] = hq;
    *(uint2*)&g_Xl[o] = lq;
}

// ---------------- HMMA bf16-split GEMM: 128x128, 2 CTAs/SM, 3-stage, 1 barrier/chunk ----------------
#define OFF_AH 0
#define OFF_AL 8192
#define OFF_BH 16384
#define OFF_BL 24576
#define STG_BYTES 32768

template<int LAYER>
__global__ __launch_bounds__(256, 2) void k_gemm_cpa(const float* __restrict__ bias) {
    constexpr bool L1 = (LAYER == 1);
    constexpr int KD = L1 ? C0_ : O1_;
    constexpr int NO = L1 ? O1_ : O2_;
    constexpr int NCH = KD / 32;

    const __nv_bfloat16* __restrict__ Ah = L1 ? g_Xh : g_A2h;
    const __nv_bfloat16* __restrict__ Al = L1 ? g_Xl : g_A2l;
    const __nv_bfloat16* __restrict__ Wh = L1 ? g_w1h : g_w2h;
    const __nv_bfloat16* __restrict__ Wl = L1 ? g_w1l : g_w2l;
    float* __restrict__ Y     = L1 ? g_Y1 : g_Y2;
    float* __restrict__ stats = L1 ? g_stats1 : g_stats2;

    extern __shared__ char sm[];
    const uint32_t smbase = (uint32_t)__cvta_generic_to_shared(sm);

    const int tid = threadIdx.x;
    const int lane = tid & 31, wid = tid >> 5;
    const int g = lane >> 2, tig = lane & 3;
    const int wm = wid & 1, wn = wid >> 1;
    const int r0 = blockIdx.x * 128;
    const int n0 = blockIdx.y * 128;

    float acc[4][4][4];
    #pragma unroll
    for (int m = 0; m < 4; m++)
        #pragma unroll
        for (int n = 0; n < 4; n++)
            #pragma unroll
            for (int j = 0; j < 4; j++) acc[m][n][j] = 0.f;

    const int a_row = wm * 64 + (lane & 15);
    const uint32_t a_colb = (uint32_t)((lane >> 4) * 16);
    const int b_row_base = wn * 32 + ((lane >> 4) << 3) + (lane & 7);
    const uint32_t b_colb = (uint32_t)(((lane >> 3) & 1) * 16);

    const int arow = tid >> 2;
    const uint32_t asegb = (uint32_t)((tid & 3) * 16);

#define CPA_CHUNK(buf, kc) do {                                                   \
        uint32_t bb = smbase + (uint32_t)((buf) * STG_BYTES);                     \
        _Pragma("unroll")                                                         \
        for (int i = 0; i < 2; i++) {                                             \
            int row = arow + i * 64;                                              \
            uint32_t doff = swz64(row, asegb);                                    \
            CPA16(bb + OFF_AH + doff, (const char*)&Ah[(size_t)(r0 + row) * KD + (kc)] + asegb); \
            CPA16(bb + OFF_AL + doff, (const char*)&Al[(size_t)(r0 + row) * KD + (kc)] + asegb); \
            CPA16(bb + OFF_BH + doff, (const char*)&Wh[(size_t)(n0 + row) * KD + (kc)] + asegb); \
            CPA16(bb + OFF_BL + doff, (const char*)&Wl[(size_t)(n0 + row) * KD + (kc)] + asegb); \
        }                                                                         \
        CPA_COMMIT();                                                             \
    } while (0)

#define COMPUTE_CHUNK(buf) do {                                                   \
        const uint32_t bufb = smbase + (uint32_t)((buf) * STG_BYTES);             \
        _Pragma("unroll")                                                         \
        for (int ko = 0; ko < 2; ko++) {                                          \
            const uint32_t kb = (uint32_t)(ko * 32);                              \
            uint32_t bh01[4], bl01[4], bh23[4], bl23[4];                          \
            ldsm4(bh01, bufb + OFF_BH + swz64(b_row_base,      b_colb + kb));     \
            ldsm4(bl01, bufb + OFF_BL + swz64(b_row_base,      b_colb + kb));     \
            ldsm4(bh23, bufb + OFF_BH + swz64(b_row_base + 16, b_colb + kb));     \
            ldsm4(bl23, bufb + OFF_BL + swz64(b_row_base + 16, b_colb + kb));     \
            _Pragma("unroll")                                                     \
            for (int mt = 0; mt < 4; mt++) {                                      \
                uint32_t ah[4], al[4];                                            \
                uint32_t ao = swz64(a_row + mt * 16, a_colb + kb);                \
                ldsm4(ah, bufb + OFF_AH + ao);                                    \
                ldsm4(al, bufb + OFF_AL + ao);                                    \
                mma16816(acc[mt][0], ah, bh01[0], bh01[1]);                       \
                mma16816(acc[mt][1], ah, bh01[2], bh01[3]);                       \
                mma16816(acc[mt][2], ah, bh23[0], bh23[1]);                       \
                mma16816(acc[mt][3], ah, bh23[2], bh23[3]);                       \
                mma16816(acc[mt][0], ah, bl01[0], bl01[1]);                       \
                mma16816(acc[mt][1], ah, bl01[2], bl01[3]);                       \
                mma16816(acc[mt][2], ah, bl23[0], bl23[1]);                       \
                mma16816(acc[mt][3], ah, bl23[2], bl23[3]);                       \
                mma16816(acc[mt][0], al, bh01[0], bh01[1]);                       \
                mma16816(acc[mt][1], al, bh01[2], bh01[3]);                       \
                mma16816(acc[mt][2], al, bh23[0], bh23[1]);                       \
                mma16816(acc[mt][3], al, bh23[2], bh23[3]);                       \
            }                                                                     \
        }                                                                         \
    } while (0)

    CPA_CHUNK(0, 0);
    CPA_CHUNK(1, 32);
    int st = 0;
    for (int ch = 0; ch < NCH; ch++) {
        if (ch + 1 < NCH) CPA_WAIT1(); else CPA_WAIT0();
        __syncthreads();
        if (ch + 2 < NCH) {
            int st2 = st + 2; if (st2 >= 3) st2 -= 3;
            CPA_CHUNK(st2, (ch + 2) * 32);
        }
        COMPUTE_CHUNK(st);
        if (++st == 3) st = 0;
    }
#undef CPA_CHUNK
#undef COMPUTE_CHUNK

    // ---- epilogue: + bias, store float, fused per-channel BN stats
    float ssum[4][2], ssq[4][2];
    #pragma unroll
    for (int nt = 0; nt < 4; nt++) { ssum[nt][0] = ssum[nt][1] = 0.f; ssq[nt][0] = ssq[nt][1] = 0.f; }

    #pragma unroll
    for (int mt = 0; mt < 4; mt++) {
        int row = r0 + wm * 64 + mt * 16 + g;
        #pragma unroll
        for (int nt = 0; nt < 4; nt++) {
            int col = n0 + wn * 32 + nt * 8 + 2 * tig;
            float bv0 = __ldg(bias + col), bv1 = __ldg(bias + col + 1);
            float v0 = acc[mt][nt][0] + bv0, v1 = acc[mt][nt][1] + bv1;
            float v2 = acc[mt][nt][2] + bv0, v3 = acc[mt][nt][3] + bv1;
            ssum[nt][0] += v0 + v2;  ssum[nt][1] += v1 + v3;
            ssq[nt][0]  += v0 * v0 + v2 * v2;
            ssq[nt][1]  += v1 * v1 + v3 * v3;
            *(float2*)&Y[(size_t)row * NO + col]       = make_float2(v0, v1);
            *(float2*)&Y[(size_t)(row + 8) * NO + col] = make_float2(v2, v3);
        }
    }

    #pragma unroll
    for (int nt = 0; nt < 4; nt++)
        #pragma unroll
        for (int c = 0; c < 2; c++) {
            float s = ssum[nt][c], q = ssq[nt][c];
            s += __shfl_xor_sync(0xFFFFFFFFu, s, 4);
            s += __shfl_xor_sync(0xFFFFFFFFu, s, 8);
            s += __shfl_xor_sync(0xFFFFFFFFu, s, 16);
            q += __shfl_xor_sync(0xFFFFFFFFu, q, 4);
            q += __shfl_xor_sync(0xFFFFFFFFu, q, 8);
            q += __shfl_xor_sync(0xFFFFFFFFu, q, 16);
            if (g == 0) {
                int col = n0 + wn * 32 + nt * 8 + 2 * tig + c;
                atomicAdd(&stats[col], s);
                atomicAdd(&stats[NO + col], q);
            }
        }
}

// ---------------- BN1 finalize (inline) + ReLU + split: Y1(float) -> A2(bf16 h/l) ----------------
__global__ __launch_bounds__(256) void k_bnsplit(const float* __restrict__ g1,
                                                 const float* __restrict__ be1) {
    __shared__ float ssc[O1_], ssh[O1_];
    int tid = threadIdx.x;
    {
        int c = tid;
        float mean = g_stats1[c] * (1.0f / ROWS_);
        float var  = g_stats1[O1_ + c] * (1.0f / ROWS_) - mean * mean;
        float rstd = rsqrtf(var + BN_EPS_);
        float sc = g1[c] * rstd;
        ssc[c] = sc;
        ssh[c] = be1[c] - mean * sc;
    }
    __syncthreads();
    int lr = tid >> 6, ln = tid & 63;
    size_t row = (size_t)blockIdx.x * 4 + lr;
    size_t base = row * O1_ + ln * 4;
    float4 y = *(const float4*)&g_Y1[base];
    int c0 = ln * 4;
    float v0 = fmaxf(fmaf(y.x, ssc[c0 + 0], ssh[c0 + 0]), 0.f);
    float v1 = fmaxf(fmaf(y.y, ssc[c0 + 1], ssh[c0 + 1]), 0.f);
    float v2 = fmaxf(fmaf(y.z, ssc[c0 + 2], ssh[c0 + 2]), 0.f);
    float v3 = fmaxf(fmaf(y.w, ssc[c0 + 3], ssh[c0 + 3]), 0.f);
    uint2 oh, ol;
    bsplit2(v0, v1, oh.x, ol.x);
    bsplit2(v2, v3, oh.y, ol.y);
    *(uint2*)&g_A2h[base] = oh;
    *(uint2*)&g_A2l[base] = ol;
}

// ---------------- BN2(inline finalize) + ReLU + transpose to output ----------------
__global__ void k_out(float* __restrict__ out,
                      const float* __restrict__ g2, const float* __restrict__ be2) {
    __shared__ float tile[32][33];
    int b = blockIdx.z;
    int n0 = blockIdx.x * 32, o0 = blockIdx.y * 32;
    int tx = threadIdx.x, ty = threadIdx.y;
    int c = o0 + tx;
    float mean = g_stats2[c] * (1.0f / ROWS_);
    float var  = g_stats2[O2_ + c] * (1.0f / ROWS_) - mean * mean;
    float rstd = rsqrtf(var + BN_EPS_);
    float sc = g2[c] * rstd;
    float sh = be2[c] - mean * sc;
    const float* src = g_Y2 + ((size_t)(b * N_ + n0)) * O2_ + o0;
    #pragma unroll
    for (int i = ty; i < 32; i += 8) {
        float v = src[(size_t)i * O2_ + tx];
        tile[i][tx] = fmaxf(fmaf(v, sc, sh), 0.f);
    }
    __syncthreads();
    float* dst = out + ((size_t)b * O2_ + o0) * N_ + n0;
    #pragma unroll
    for (int i = ty; i < 32; i += 8)
        dst[(size_t)i * N_ + tx] = tile[tx][i];
}

// ---------------- launch ----------------
extern "C" void kernel_launch(void* const* d_in, const int* in_sizes, int n_in,
                              void* d_out, int out_size) {
    (void)in_sizes; (void)n_in; (void)out_size;
    const float* xyz1    = (const float*)d_in[0];
    const float* xyz2    = (const float*)d_in[1];
    const float* points1 = (const float*)d_in[2];
    const float* points2 = (const float*)d_in[3];
    const float* w1  = (const float*)d_in[4];
    const float* b1  = (const float*)d_in[5];
    const float* g1  = (const float*)d_in[6];
    const float* be1 = (const float*)d_in[7];
    const float* w2  = (const float*)d_in[8];
    const float* b2  = (const float*)d_in[9];
    const float* g2  = (const float*)d_in[10];
    const float* be2 = (const float*)d_in[11];
    float* out = (float*)d_out;

    const int SMEM = 3 * STG_BYTES;   // 98304 per CTA; 2 CTAs = 192KB <= 228KB
    cudaFuncSetAttribute(k_gemm_cpa<1>, cudaFuncAttributeMaxDynamicSharedMemorySize, SMEM);
    cudaFuncSetAttribute(k_gemm_cpa<2>, cudaFuncAttributeMaxDynamicSharedMemorySize, SMEM);

    k_prep<<<TOT_BLKS, 256>>>(xyz1, xyz2, w1, w2, points2, points1);               // 0
    k_interp<<<ROWS_ / 4, 256>>>(xyz1);                                            // 1
    k_gemm_cpa<1><<<dim3(ROWS_ / 128, 2), 256, SMEM>>>(b1);                        // 2
    k_bnsplit<<<ROWS_ / 4, 256>>>(g1, be1);                                        // 3
    k_gemm_cpa<2><<<dim3(ROWS_ / 128, 1), 256, SMEM>>>(b2);                        // 4
    k_out<<<dim3(N_ / 32, O2_ / 32, B_), dim3(32, 8)>>>(out, g2, be2);             // 5
}

// round 16
// speedup vs baseline: 1.2190x; 1.0717x over previous
#include <cuda_runtime.h>
#include <cuda_bf16.h>
#include <cstdint>

// Problem constants
#define B_    8
#define N_    8192
#define S_    2048
#define D1_   128
#define D2_   256
#define C0_   384          // D1 + D2
#define O1_   256
#define O2_   128
#define ROWS_ 65536        // B_ * N_
#define BN_EPS_ 1e-5f
#define NPART 8
#define SPART (S_ / NPART)   // 256
#define NCAND (NPART * 3)    // 24

// ---------------- device scratch (no cudaMalloc allowed) ----------------
__device__ __align__(16) __nv_bfloat16 g_Xh[(size_t)ROWS_ * C0_];   // concat hi
__device__ __align__(16) __nv_bfloat16 g_Xl[(size_t)ROWS_ * C0_];   // concat lo
__device__ __align__(16) float g_Y1[(size_t)ROWS_ * O1_];           // layer1 pre-BN
__device__ __align__(16) __nv_bfloat16 g_A2h[(size_t)ROWS_ * O1_];  // BN1+ReLU split hi
__device__ __align__(16) __nv_bfloat16 g_A2l[(size_t)ROWS_ * O1_];  // BN1+ReLU split lo
__device__ __align__(16) float g_Y2[(size_t)ROWS_ * O2_];           // layer2 pre-BN
__device__ __align__(16) float g_f2[(size_t)B_ * S_ * D2_];         // points2 transposed
__device__ __align__(16) float g_cd[(size_t)ROWS_ * NCAND];
__device__ __align__(16) int   g_ci[(size_t)ROWS_ * NCAND];
__device__ float  g_stats1[2 * O1_];
__device__ float  g_stats2[2 * O2_];
__device__ __align__(16) __nv_bfloat16 g_w1h[O1_ * C0_], g_w1l[O1_ * C0_];
__device__ __align__(16) __nv_bfloat16 g_w2h[O2_ * O1_], g_w2l[O2_ * O1_];

// ---------------- helpers ----------------
__device__ __forceinline__ void bsplit2(float a, float b, uint32_t& h, uint32_t& l) {
    __nv_bfloat162 hv, lv;
    hv.x = __float2bfloat16_rn(a);
    hv.y = __float2bfloat16_rn(b);
    lv.x = __float2bfloat16_rn(a - __bfloat162float(hv.x));
    lv.y = __float2bfloat16_rn(b - __bfloat162float(hv.y));
    h = *reinterpret_cast<uint32_t*>(&hv);
    l = *reinterpret_cast<uint32_t*>(&lv);
}

__device__ __forceinline__ void mma16816(float c[4], const uint32_t a[4],
                                         uint32_t b0, uint32_t b1) {
    asm volatile(
        "mma.sync.aligned.m16n8k16.row.col.f32.bf16.bf16.f32 "
        "{%0,%1,%2,%3}, {%4,%5,%6,%7}, {%8,%9}, {%0,%1,%2,%3};"
        : "+f"(c[0]), "+f"(c[1]), "+f"(c[2]), "+f"(c[3])
        : "r"(a[0]), "r"(a[1]), "r"(a[2]), "r"(a[3]), "r"(b0), "r"(b1));
}

__device__ __forceinline__ void ldsm4(uint32_t r[4], uint32_t addr) {
    asm volatile("ldmatrix.sync.aligned.m8n8.x4.shared.b16 {%0,%1,%2,%3}, [%4];"
        : "=r"(r[0]), "=r"(r[1]), "=r"(r[2]), "=r"(r[3]) : "r"(addr));
}

#define CPA16(dst, src) \
    asm volatile("cp.async.cg.shared.global [%0], [%1], 16;" :: "r"(dst), "l"(src))
#define CPA_COMMIT() asm volatile("cp.async.commit_group;" ::: "memory")
#define CPA_WAIT0()  asm volatile("cp.async.wait_group 0;" ::: "memory")
#define CPA_WAIT1()  asm volatile("cp.async.wait_group 1;" ::: "memory")

// row-swizzled 64B-row smem layout: addr = row*64 + (colbyte ^ ((row*8)&0x30))
__device__ __forceinline__ uint32_t swz64(int row, uint32_t colbyte) {
    return (uint32_t)(row * 64) + (colbyte ^ (uint32_t)((row * 8) & 0x30));
}

// ---------------- fused prep + 3-NN (sequential layout, proven R13) ----------------
#define NN_BLKS  2048
#define PRE_BLKS 384
#define TRF2_BLKS 4096
#define TRF1_BLKS 8192
__global__ __launch_bounds__(256) void k_prep(const float* __restrict__ xyz1,
                      const float* __restrict__ xyz2,
                      const float* __restrict__ w1, const float* __restrict__ w2,
                      const float* __restrict__ points2, const float* __restrict__ points1) {
    __shared__ float tile[32][33];
    __shared__ float4 sp[SPART];
    int bid = blockIdx.x;
    int tid = threadIdx.x;
    if (bid < NN_BLKS) {
        int b    = bid >> 8;
        int rem  = bid & 255;
        int part = rem >> 5;
        int n    = (rem & 31) * 256 + tid;
        {
            const float* p = xyz2 + (size_t)b * 3 * S_ + part * SPART;
            float x = p[tid], y = p[S_ + tid], z = p[2 * S_ + tid];
            sp[tid] = make_float4(x, y, z, x * x + y * y + z * z);
        }
        __syncthreads();

        const float* q = xyz1 + (size_t)b * 3 * N_;
        float x = q[n], y = q[N_ + n], z = q[2 * N_ + n];
        float nx = -2.f * x, ny = -2.f * y, nz = -2.f * z;

        float d0 = 1e30f, d1 = 1e30f, d2 = 1e30f;
        int i0 = 0, i1 = 0, i2 = 0;
        #pragma unroll 8
        for (int s = 0; s < SPART; s++) {
            float4 p = sp[s];
            float d = fmaf(p.x, nx, fmaf(p.y, ny, fmaf(p.z, nz, p.w)));
            if (d < d2) {
                if (d < d1) {
                    d2 = d1; i2 = i1;
                    if (d < d0) { d1 = d0; i1 = i0; d0 = d; i0 = s; }
                    else        { d1 = d;  i1 = s; }
                } else { d2 = d; i2 = s; }
            }
        }
        size_t row = (size_t)b * N_ + n;
        size_t o = row * NCAND + part * 3;
        int base = part * SPART;
        g_cd[o + 0] = d0; g_cd[o + 1] = d1; g_cd[o + 2] = d2;
        g_ci[o + 0] = base + i0; g_ci[o + 1] = base + i1; g_ci[o + 2] = base + i2;
    } else if (bid < NN_BLKS + PRE_BLKS) {
        int t = (bid - NN_BLKS) * 256 + tid;
        if (t < 2 * O1_) g_stats1[t] = 0.f;
        if (t < 2 * O2_) g_stats2[t] = 0.f;
        if (t < O1_ * C0_) {
            float v = w1[t];
            __nv_bfloat16 h = __float2bfloat16_rn(v);
            g_w1h[t] = h;
            g_w1l[t] = __float2bfloat16_rn(v - __bfloat162float(h));
        }
        if (t < O2_ * O1_) {
            float v = w2[t];
            __nv_bfloat16 h = __float2bfloat16_rn(v);
            g_w2h[t] = h;
            g_w2l[t] = __float2bfloat16_rn(v - __bfloat162float(h));
        }
    } else if (bid < NN_BLKS + PRE_BLKS + TRF2_BLKS) {
        int rel = bid - NN_BLKS - PRE_BLKS;
        int s0 = (rel & 63) * 32;
        int d0 = ((rel >> 6) & 7) * 32;
        int b  = rel >> 9;
        int tx = tid & 31, ty = tid >> 5;
        const float* src = points2 + ((size_t)b * D2_ + d0) * S_ + s0;
        #pragma unroll
        for (int i = ty; i < 32; i += 8)
            tile[i][tx] = src[(size_t)i * S_ + tx];
        __syncthreads();
        float* dst = g_f2 + ((size_t)b * S_ + s0) * D2_ + d0;
        #pragma unroll
        for (int i = ty; i < 32; i += 8)
            dst[(size_t)i * D2_ + tx] = tile[tx][i];
    } else {
        int rel = bid - NN_BLKS - PRE_BLKS - TRF2_BLKS;
        int n0 = (rel & 255) * 32;
        int d0 = ((rel >> 8) & 3) * 32;
        int b  = rel >> 10;
        int tx = tid & 31, ty = tid >> 5;
        const float* src = points1 + ((size_t)b * D1_ + d0) * N_ + n0;
        #pragma unroll
        for (int i = ty; i < 32; i += 8)
            tile[i][tx] = src[(size_t)i * N_ + tx];
        __syncthreads();
        size_t base = ((size_t)(b * N_ + n0)) * C0_ + d0;
        #pragma unroll
        for (int i = ty; i < 32; i += 8) {
            float v = tile[tx][i];
            __nv_bfloat16 h = __float2bfloat16_rn(v);
            g_Xh[base + (size_t)i * C0_ + tx] = h;
            g_Xl[base + (size_t)i * C0_ + tx] = __float2bfloat16_rn(v - __bfloat162float(h));
        }
    }
}

// ---------------- fused merge(24->3) + gather + interpolate -> split bf16 ----------------
// 8 rows per block; each thread gathers 2 row-quarters (MLP 6).
__global__ __launch_bounds__(256) void k_interp(const float* __restrict__ xyz1) {
    __shared__ int   sidx[8][3];
    __shared__ float swt [8][3];
    int t = threadIdx.x;
    if (t < 8) {
        unsigned row = blockIdx.x * 8 + t;
        int b = row / N_, n = row % N_;
        float d0 = 1e30f, d1 = 1e30f, d2 = 1e30f;
        int i0 = 0, i1 = 0, i2 = 0;
        const float* cd = g_cd + (size_t)row * NCAND;
        const int*   ci = g_ci + (size_t)row * NCAND;
        #pragma unroll
        for (int j = 0; j < NCAND; j++) {
            float d = cd[j]; int ix = ci[j];
            if (d < d2) {
                if (d < d1) {
                    d2 = d1; i2 = i1;
                    if (d < d0) { d1 = d0; i1 = i0; d0 = d; i0 = ix; }
                    else        { d1 = d;  i1 = ix; }
                } else { d2 = d; i2 = ix; }
            }
        }
        const float* q = xyz1 + (size_t)b * 3 * N_;
        float x = q[n], y = q[N_ + n], z = q[2 * N_ + n];
        float r1 = x * x + y * y + z * z;
        float t0 = fmaxf(d0 + r1, 1e-10f);
        float t1 = fmaxf(d1 + r1, 1e-10f);
        float t2 = fmaxf(d2 + r1, 1e-10f);
        float w0 = 1.f / t0, w1 = 1.f / t1, w2 = 1.f / t2;
        float inv = 1.f / (w0 + w1 + w2);
        sidx[t][0] = i0; sidx[t][1] = i1; sidx[t][2] = i2;
        swt [t][0] = w0 * inv; swt[t][1] = w1 * inv; swt[t][2] = w2 * inv;
    }
    __syncthreads();
    #pragma unroll
    for (int half = 0; half < 2; half++) {
        int item = t + half * 256;          // 0..511
        int lr = item >> 6, ln = item & 63;
        unsigned row = blockIdx.x * 8 + lr;
        int b = row / N_;
        int  i0 = sidx[lr][0], i1 = sidx[lr][1], i2 = sidx[lr][2];
        float w0 = swt[lr][0], w1 = swt[lr][1], w2 = swt[lr][2];
        const float4* f = (const float4*)(g_f2 + (size_t)b * S_ * D2_);
        float4 v0 = f[(size_t)i0 * 64 + ln];
        float4 v1 = f[(size_t)i1 * 64 + ln];
        float4 v2 = f[(size_t)i2 * 64 + ln];
        float4 v;
        v.x = w0 * v0.x + w1 * v1.x + w2 * v2.x;
        v.y = w0 * v0.y + w1 * v1.y + w2 * v2.y;
        v.z = w0 * v0.z + w1 * v1.z + w2 * v2.z;
        v.w = w0 * v0.w + w1 * v1.w + w2 * v2.w;
        uint2 hq, lq;
        bsplit2(v.x, v.y, hq.x, lq.x);
        bsplit2(v.z, v.w, hq.y, lq.y);
        size_t o = (size_t)row * C0_ + D1_ + ln * 4;
        *(uint2*)&g_Xh[o] = hq;
        *(uint2*)&g_Xl[o] = lq;
    }
}

// ---------------- HMMA bf16-split GEMM: 128x128, 2 CTAs/SM, 3-stage, 1 barrier/chunk ----------------
#define OFF_AH 0
#define OFF_AL 8192
#define OFF_BH 16384
#define OFF_BL 24576
#define STG_BYTES 32768

template<int LAYER>
__global__ __launch_bounds__(256, 2) void k_gemm_cpa(const float* __restrict__ bias) {
    constexpr bool L1 = (LAYER == 1);
    constexpr int KD = L1 ? C0_ : O1_;
    constexpr int NO = L1 ? O1_ : O2_;
    constexpr int NCH = KD / 32;

    const __nv_bfloat16* __restrict__ Ah = L1 ? g_Xh : g_A2h;
    const __nv_bfloat16* __restrict__ Al = L1 ? g_Xl : g_A2l;
    const __nv_bfloat16* __restrict__ Wh = L1 ? g_w1h : g_w2h;
    const __nv_bfloat16* __restrict__ Wl = L1 ? g_w1l : g_w2l;
    float* __restrict__ Y     = L1 ? g_Y1 : g_Y2;
    float* __restrict__ stats = L1 ? g_stats1 : g_stats2;

    extern __shared__ char sm[];
    const uint32_t smbase = (uint32_t)__cvta_generic_to_shared(sm);

    const int tid = threadIdx.x;
    const int lane = tid & 31, wid = tid >> 5;
    const int g = lane >> 2, tig = lane & 3;
    const int wm = wid & 1, wn = wid >> 1;
    const int r0 = blockIdx.x * 128;
    const int n0 = blockIdx.y * 128;

    float acc[4][4][4];
    #pragma unroll
    for (int m = 0; m < 4; m++)
        #pragma unroll
        for (int n = 0; n < 4; n++)
            #pragma unroll
            for (int j = 0; j < 4; j++) acc[m][n][j] = 0.f;

    const int a_row = wm * 64 + (lane & 15);
    const uint32_t a_colb = (uint32_t)((lane >> 4) * 16);
    const int b_row_base = wn * 32 + ((lane >> 4) << 3) + (lane & 7);
    const uint32_t b_colb = (uint32_t)(((lane >> 3) & 1) * 16);

    const int arow = tid >> 2;
    const uint32_t asegb = (uint32_t)((tid & 3) * 16);

#define CPA_CHUNK(buf, kc) do {                                                   \
        uint32_t bb = smbase + (uint32_t)((buf) * STG_BYTES);                     \
        _Pragma("unroll")                                                         \
        for (int i = 0; i < 2; i++) {                                             \
            int row = arow + i * 64;                                              \
            uint32_t doff = swz64(row, asegb);                                    \
            CPA16(bb + OFF_AH + doff, (const char*)&Ah[(size_t)(r0 + row) * KD + (kc)] + asegb); \
            CPA16(bb + OFF_AL + doff, (const char*)&Al[(size_t)(r0 + row) * KD + (kc)] + asegb); \
            CPA16(bb + OFF_BH + doff, (const char*)&Wh[(size_t)(n0 + row) * KD + (kc)] + asegb); \
            CPA16(bb + OFF_BL + doff, (const char*)&Wl[(size_t)(n0 + row) * KD + (kc)] + asegb); \
        }                                                                         \
        CPA_COMMIT();                                                             \
    } while (0)

#define COMPUTE_CHUNK(buf) do {                                                   \
        const uint32_t bufb = smbase + (uint32_t)((buf) * STG_BYTES);             \
        _Pragma("unroll")                                                         \
        for (int ko = 0; ko < 2; ko++) {                                          \
            const uint32_t kb = (uint32_t)(ko * 32);                              \
            uint32_t bh01[4], bl01[4], bh23[4], bl23[4];                          \
            ldsm4(bh01, bufb + OFF_BH + swz64(b_row_base,      b_colb + kb));     \
            ldsm4(bl01, bufb + OFF_BL + swz64(b_row_base,      b_colb + kb));     \
            ldsm4(bh23, bufb + OFF_BH + swz64(b_row_base + 16, b_colb + kb));     \
            ldsm4(bl23, bufb + OFF_BL + swz64(b_row_base + 16, b_colb + kb));     \
            _Pragma("unroll")                                                     \
            for (int mt = 0; mt < 4; mt++) {                                      \
                uint32_t ah[4], al[4];                                            \
                uint32_t ao = swz64(a_row + mt * 16, a_colb + kb);                \
                ldsm4(ah, bufb + OFF_AH + ao);                                    \
                ldsm4(al, bufb + OFF_AL + ao);                                    \
                mma16816(acc[mt][0], ah, bh01[0], bh01[1]);                       \
                mma16816(acc[mt][1], ah, bh01[2], bh01[3]);                       \
                mma16816(acc[mt][2], ah, bh23[0], bh23[1]);                       \
                mma16816(acc[mt][3], ah, bh23[2], bh23[3]);                       \
                mma16816(acc[mt][0], ah, bl01[0], bl01[1]);                       \
                mma16816(acc[mt][1], ah, bl01[2], bl01[3]);                       \
                mma16816(acc[mt][2], ah, bl23[0], bl23[1]);                       \
                mma16816(acc[mt][3], ah, bl23[2], bl23[3]);                       \
                mma16816(acc[mt][0], al, bh01[0], bh01[1]);                       \
                mma16816(acc[mt][1], al, bh01[2], bh01[3]);                       \
                mma16816(acc[mt][2], al, bh23[0], bh23[1]);                       \
                mma16816(acc[mt][3], al, bh23[2], bh23[3]);                       \
            }                                                                     \
        }                                                                         \
    } while (0)

    CPA_CHUNK(0, 0);
    CPA_CHUNK(1, 32);
    int st = 0;
    for (int ch = 0; ch < NCH; ch++) {
        if (ch + 1 < NCH) CPA_WAIT1(); else CPA_WAIT0();
        __syncthreads();
        if (ch + 2 < NCH) {
            int st2 = st + 2; if (st2 >= 3) st2 -= 3;
            CPA_CHUNK(st2, (ch + 2) * 32);
        }
        COMPUTE_CHUNK(st);
        if (++st == 3) st = 0;
    }
#undef CPA_CHUNK
#undef COMPUTE_CHUNK

    // ---- epilogue: + bias, store float, fused per-channel BN stats
    float ssum[4][2], ssq[4][2];
    #pragma unroll
    for (int nt = 0; nt < 4; nt++) { ssum[nt][0] = ssum[nt][1] = 0.f; ssq[nt][0] = ssq[nt][1] = 0.f; }

    #pragma unroll
    for (int mt = 0; mt < 4; mt++) {
        int row = r0 + wm * 64 + mt * 16 + g;
        #pragma unroll
        for (int nt = 0; nt < 4; nt++) {
            int col = n0 + wn * 32 + nt * 8 + 2 * tig;
            float bv0 = __ldg(bias + col), bv1 = __ldg(bias + col + 1);
            float v0 = acc[mt][nt][0] + bv0, v1 = acc[mt][nt][1] + bv1;
            float v2 = acc[mt][nt][2] + bv0, v3 = acc[mt][nt][3] + bv1;
            ssum[nt][0] += v0 + v2;  ssum[nt][1] += v1 + v3;
            ssq[nt][0]  += v0 * v0 + v2 * v2;
            ssq[nt][1]  += v1 * v1 + v3 * v3;
            *(float2*)&Y[(size_t)row * NO + col]       = make_float2(v0, v1);
            *(float2*)&Y[(size_t)(row + 8) * NO + col] = make_float2(v2, v3);
        }
    }

    #pragma unroll
    for (int nt = 0; nt < 4; nt++)
        #pragma unroll
        for (int c = 0; c < 2; c++) {
            float s = ssum[nt][c], q = ssq[nt][c];
            s += __shfl_xor_sync(0xFFFFFFFFu, s, 4);
            s += __shfl_xor_sync(0xFFFFFFFFu, s, 8);
            s += __shfl_xor_sync(0xFFFFFFFFu, s, 16);
            q += __shfl_xor_sync(0xFFFFFFFFu, q, 4);
            q += __shfl_xor_sync(0xFFFFFFFFu, q, 8);
            q += __shfl_xor_sync(0xFFFFFFFFu, q, 16);
            if (g == 0) {
                int col = n0 + wn * 32 + nt * 8 + 2 * tig + c;
                atomicAdd(&stats[col], s);
                atomicAdd(&stats[NO + col], q);
            }
        }
}

// ---------------- BN1 finalize (inline) + ReLU + split: Y1(float) -> A2(bf16 h/l) ----------------
__global__ __launch_bounds__(256) void k_bnsplit(const float* __restrict__ g1,
                                                 const float* __restrict__ be1) {
    __shared__ float ssc[O1_], ssh[O1_];
    int tid = threadIdx.x;
    {
        int c = tid;
        float mean = g_stats1[c] * (1.0f / ROWS_);
        float var  = g_stats1[O1_ + c] * (1.0f / ROWS_) - mean * mean;
        float rstd = rsqrtf(var + BN_EPS_);
        float sc = g1[c] * rstd;
        ssc[c] = sc;
        ssh[c] = be1[c] - mean * sc;
    }
    __syncthreads();
    int lr = tid >> 6, ln = tid & 63;
    size_t row = (size_t)blockIdx.x * 4 + lr;
    size_t base = row * O1_ + ln * 4;
    float4 y = *(const float4*)&g_Y1[base];
    int c0 = ln * 4;
    float v0 = fmaxf(fmaf(y.x, ssc[c0 + 0], ssh[c0 + 0]), 0.f);
    float v1 = fmaxf(fmaf(y.y, ssc[c0 + 1], ssh[c0 + 1]), 0.f);
    float v2 = fmaxf(fmaf(y.z, ssc[c0 + 2], ssh[c0 + 2]), 0.f);
    float v3 = fmaxf(fmaf(y.w, ssc[c0 + 3], ssh[c0 + 3]), 0.f);
    uint2 oh, ol;
    bsplit2(v0, v1, oh.x, ol.x);
    bsplit2(v2, v3, oh.y, ol.y);
    *(uint2*)&g_A2h[base] = oh;
    *(uint2*)&g_A2l[base] = ol;
}

// ---------------- BN2(inline finalize) + ReLU + transpose to output ----------------
__global__ void k_out(float* __restrict__ out,
                      const float* __restrict__ g2, const float* __restrict__ be2) {
    __shared__ float tile[32][33];
    int b = blockIdx.z;
    int n0 = blockIdx.x * 32, o0 = blockIdx.y * 32;
    int tx = threadIdx.x, ty = threadIdx.y;
    int c = o0 + tx;
    float mean = g_stats2[c] * (1.0f / ROWS_);
    float var  = g_stats2[O2_ + c] * (1.0f / ROWS_) - mean * mean;
    float rstd = rsqrtf(var + BN_EPS_);
    float sc = g2[c] * rstd;
    float sh = be2[c] - mean * sc;
    const float* src = g_Y2 + ((size_t)(b * N_ + n0)) * O2_ + o0;
    #pragma unroll
    for (int i = ty; i < 32; i += 8) {
        float v = src[(size_t)i * O2_ + tx];
        tile[i][tx] = fmaxf(fmaf(v, sc, sh), 0.f);
    }
    __syncthreads();
    float* dst = out + ((size_t)b * O2_ + o0) * N_ + n0;
    #pragma unroll
    for (int i = ty; i < 32; i += 8)
        dst[(size_t)i * N_ + tx] = tile[tx][i];
}

// ---------------- launch ----------------
extern "C" void kernel_launch(void* const* d_in, const int* in_sizes, int n_in,
                              void* d_out, int out_size) {
    (void)in_sizes; (void)n_in; (void)out_size;
    const float* xyz1    = (const float*)d_in[0];
    const float* xyz2    = (const float*)d_in[1];
    const float* points1 = (const float*)d_in[2];
    const float* points2 = (const float*)d_in[3];
    const float* w1  = (const float*)d_in[4];
    const float* b1  = (const float*)d_in[5];
    const float* g1  = (const float*)d_in[6];
    const float* be1 = (const float*)d_in[7];
    const float* w2  = (const float*)d_in[8];
    const float* b2  = (const float*)d_in[9];
    const float* g2  = (const float*)d_in[10];
    const float* be2 = (const float*)d_in[11];
    float* out = (float*)d_out;

    const int SMEM = 3 * STG_BYTES;   // 98304 per CTA; 2 CTAs = 192KB <= 228KB
    cudaFuncSetAttribute(k_gemm_cpa<1>, cudaFuncAttributeMaxDynamicSharedMemorySize, SMEM);
    cudaFuncSetAttribute(k_gemm_cpa<2>, cudaFuncAttributeMaxDynamicSharedMemorySize, SMEM);

    k_prep<<<NN_BLKS + PRE_BLKS + TRF2_BLKS + TRF1_BLKS, 256>>>(
        xyz1, xyz2, w1, w2, points2, points1);                                     // 0
    k_interp<<<ROWS_ / 8, 256>>>(xyz1);                                            // 1
    k_gemm_cpa<1><<<dim3(ROWS_ / 128, 2), 256, SMEM>>>(b1);                        // 2
    k_bnsplit<<<ROWS_ / 4, 256>>>(g1, be1);                                        // 3
    k_gemm_cpa<2><<<dim3(ROWS_ / 128, 1), 256, SMEM>>>(b2);                        // 4
    k_out<<<dim3(N_ / 32, O2_ / 32, B_), dim3(32, 8)>>>(out, g2, be2);             // 5
}